// round 4
// baseline (speedup 1.0000x reference)
#include <cuda_runtime.h>
#include <cuda_bf16.h>
#include <math.h>

// ---------------- problem constants ----------------
#define N_NODES   100000
#define N_EDGES   3200000
#define N_FEAT    128
#define HIDDEN    64
#define N_CLASSES 3
#define N_GRAPHS  512
#define BN_EPS    1e-5f

#define SCAN_BS   1024
#define SCAN_NB   ((N_NODES + SCAN_BS - 1) / SCAN_BS)   // 98

// ---------------- device scratch (no allocation allowed) ----------------
__device__ __align__(16) float g_h1[(size_t)N_NODES * HIDDEN];   // X@W1, later h2@W2
__device__ __align__(16) float g_h2[(size_t)N_NODES * HIDDEN];   // conv1 output (post BN/ReLU)
__device__ int   g_csr_src[N_EDGES];
__device__ float g_csr_w[N_EDGES];
__device__ int   g_ptr[N_NODES + 1];
__device__ int   g_cnt[N_NODES];      // in-degree (no self loop)
__device__ int   g_cursor[N_NODES];
__device__ float g_dinv[N_NODES];
__device__ int   g_bsum[SCAN_NB + 1];
__device__ float g_pooled[N_GRAPHS * HIDDEN];
__device__ float g_gcount[N_GRAPHS];
__device__ __align__(16) float g_bnA1[HIDDEN], g_bnB1[HIDDEN], g_bnA2[HIDDEN], g_bnB2[HIDDEN];
__device__ int   g_idx64;             // 1 if edge/batch buffers are int64, 0 if int32

// flag-guarded index load (uniform branch; g_idx64 set before any use)
__device__ __forceinline__ int load_idx(const void* p, size_t i) {
    if (g_idx64) return (int)((const long long*)p)[i];
    return ((const int*)p)[i];
}

// ---------------- dtype detection ----------------
__global__ void k_detect(const void* ei) {
    if (threadIdx.x == 0) {
        const long long* p = (const long long*)ei;
        int ok = 1;
        for (int i = 0; i < 16; i++) {
            long long v = p[i];
            if (v < 0 || v >= N_NODES) ok = 0;
        }
        g_idx64 = ok;
    }
}

// ---------------- init ----------------
__global__ void k_init() {
    int i = blockIdx.x * blockDim.x + threadIdx.x;
    if (i < N_NODES) { g_cnt[i] = 0; g_cursor[i] = 0; }
    if (i < N_GRAPHS * HIDDEN) g_pooled[i] = 0.0f;
    if (i < N_GRAPHS) g_gcount[i] = 0.0f;
}

// histogram of dst
__global__ void k_hist(const void* __restrict__ ei) {
    int e = blockIdx.x * blockDim.x + threadIdx.x;
    if (e < N_EDGES) {
        int d = load_idx(ei, (size_t)N_EDGES + e);
        atomicAdd(&g_cnt[d], 1);
    }
}

// dinv = rsqrt(indeg+1); also accumulate per-graph node counts
__global__ void k_dinv(const void* __restrict__ batch) {
    int i = blockIdx.x * blockDim.x + threadIdx.x;
    if (i < N_NODES) {
        g_dinv[i] = rsqrtf((float)(g_cnt[i] + 1));
        atomicAdd(&g_gcount[load_idx(batch, i)], 1.0f);
    }
}

// ---------------- 3-phase exclusive scan of g_cnt -> g_ptr ----------------
__global__ void k_scanA() {
    __shared__ int sm[SCAN_BS];
    int i = blockIdx.x * SCAN_BS + threadIdx.x;
    int v = (i < N_NODES) ? g_cnt[i] : 0;
    sm[threadIdx.x] = v;
    __syncthreads();
    for (int off = 1; off < SCAN_BS; off <<= 1) {
        int t = (threadIdx.x >= off) ? sm[threadIdx.x - off] : 0;
        __syncthreads();
        sm[threadIdx.x] += t;
        __syncthreads();
    }
    if (i < N_NODES) g_ptr[i] = sm[threadIdx.x] - v;  // exclusive
    if (threadIdx.x == SCAN_BS - 1) g_bsum[blockIdx.x] = sm[SCAN_BS - 1];
}

__global__ void k_scanB() {
    if (threadIdx.x == 0) {
        int acc = 0;
        for (int b = 0; b < SCAN_NB; b++) { int t = g_bsum[b]; g_bsum[b] = acc; acc += t; }
    }
}

__global__ void k_scanC() {
    int i = blockIdx.x * SCAN_BS + threadIdx.x;
    if (i < N_NODES) g_ptr[i] += g_bsum[blockIdx.x];
    if (i == 0) g_ptr[N_NODES] = N_EDGES;
}

// fill CSR (sorted by dst; order within node nondeterministic — sums are fp-robust)
__global__ void k_fill(const void* __restrict__ ei) {
    int e = blockIdx.x * blockDim.x + threadIdx.x;
    if (e < N_EDGES) {
        int s = load_idx(ei, e);
        int d = load_idx(ei, (size_t)N_EDGES + e);
        int pos = atomicAdd(&g_cursor[d], 1);
        int idx = g_ptr[d] + pos;
        g_csr_src[idx] = s;
        g_csr_w[idx]   = g_dinv[s] * g_dinv[d];
    }
}

// fold bias + batchnorm into per-feature (A, B):  out = relu(acc*A + B)
__global__ void k_bnprep(const float* b1, const float* gm1, const float* bt1,
                         const float* rm1, const float* rv1,
                         const float* b2, const float* gm2, const float* bt2,
                         const float* rm2, const float* rv2) {
    int t = threadIdx.x;
    if (t < HIDDEN) {
        float a1 = gm1[t] * rsqrtf(rv1[t] + BN_EPS);
        g_bnA1[t] = a1;
        g_bnB1[t] = (b1[t] - rm1[t]) * a1 + bt1[t];
        float a2 = gm2[t] * rsqrtf(rv2[t] + BN_EPS);
        g_bnA2[t] = a2;
        g_bnB2[t] = (b2[t] - rm2[t]) * a2 + bt2[t];
    }
}

// ---------------- GEMM: g_h1[M,64] = A[M,K] @ W[K,64], fp32, 64x64 tile ----------------
// SRC==0: A = external pointer (x).  SRC==1: A = g_h2.
template<int K, int SRC>
__global__ void k_gemm64(const float* __restrict__ Aext, const float* __restrict__ W,
                         int M) {
    constexpr int KC = 64;
    __shared__ float sB[KC * 64];        // W chunk, row-major [k][64]
    __shared__ float sAT[KC * 68];       // A chunk transposed [k][row], pad 68
    const float* A = (SRC == 0) ? Aext : g_h2;
    float* C = g_h1;
    int row0 = blockIdx.x * 64;
    int t  = threadIdx.x;
    int rq = t >> 4;      // 0..15 -> 4 rows each
    int cq = t & 15;      // 0..15 -> 4 cols each
    float acc[4][4];
    #pragma unroll
    for (int i = 0; i < 4; i++)
        #pragma unroll
        for (int j = 0; j < 4; j++) acc[i][j] = 0.0f;

    for (int k0 = 0; k0 < K; k0 += KC) {
        const float4* Wv = (const float4*)(W + (size_t)k0 * 64);
        float4* sBv = (float4*)sB;
        for (int i = t; i < KC * 16; i += 256) sBv[i] = Wv[i];
        for (int i = t; i < 64 * (KC / 4); i += 256) {
            int r  = i >> 4;            // 0..63
            int kk = (i & 15) << 2;     // 0,4,...,60
            float4 v = make_float4(0.f, 0.f, 0.f, 0.f);
            int row = row0 + r;
            if (row < M) v = *(const float4*)(A + (size_t)row * K + k0 + kk);
            sAT[(kk + 0) * 68 + r] = v.x;
            sAT[(kk + 1) * 68 + r] = v.y;
            sAT[(kk + 2) * 68 + r] = v.z;
            sAT[(kk + 3) * 68 + r] = v.w;
        }
        __syncthreads();
        #pragma unroll
        for (int k = 0; k < KC; k++) {
            float4 a = *(const float4*)&sAT[k * 68 + rq * 4];
            float4 b = *(const float4*)&sB[k * 64 + cq * 4];
            acc[0][0] += a.x * b.x; acc[0][1] += a.x * b.y; acc[0][2] += a.x * b.z; acc[0][3] += a.x * b.w;
            acc[1][0] += a.y * b.x; acc[1][1] += a.y * b.y; acc[1][2] += a.y * b.z; acc[1][3] += a.y * b.w;
            acc[2][0] += a.z * b.x; acc[2][1] += a.z * b.y; acc[2][2] += a.z * b.z; acc[2][3] += a.z * b.w;
            acc[3][0] += a.w * b.x; acc[3][1] += a.w * b.y; acc[3][2] += a.w * b.z; acc[3][3] += a.w * b.w;
        }
        __syncthreads();
    }
    #pragma unroll
    for (int ii = 0; ii < 4; ii++) {
        int row = row0 + rq * 4 + ii;
        if (row < M) {
            float4 o = make_float4(acc[ii][0], acc[ii][1], acc[ii][2], acc[ii][3]);
            *(float4*)&C[(size_t)row * 64 + cq * 4] = o;
        }
    }
}

// ---------------- conv (pull, warp-per-node), reads g_h1 ----------------
// POOL==0: g_h2[n] = relu((sum + self)*A1 + B1)
// POOL==1: atomicAdd relu((sum+self)*A2 + B2) into g_pooled[batch[n]]
template<int POOL>
__global__ void k_conv(const void* __restrict__ batch) {
    int warp = (blockIdx.x * blockDim.x + threadIdx.x) >> 5;
    int lane = threadIdx.x & 31;
    if (warp >= N_NODES) return;
    int n = warp;
    const float2* hin2 = (const float2*)g_h1;

    float2 acc = make_float2(0.f, 0.f);
    int start = g_ptr[n];
    int end   = g_ptr[n + 1];

    int e = start;
    for (; e + 32 <= end; e += 32) {
        int   s = g_csr_src[e + lane];
        float w = g_csr_w[e + lane];
        #pragma unroll
        for (int j = 0; j < 32; j++) {
            int   sj = __shfl_sync(0xffffffffu, s, j);
            float wj = __shfl_sync(0xffffffffu, w, j);
            float2 hv = hin2[(size_t)sj * 32 + lane];
            acc.x += hv.x * wj;
            acc.y += hv.y * wj;
        }
    }
    int rem = end - e;
    if (rem > 0) {
        int   s = (lane < rem) ? g_csr_src[e + lane] : 0;
        float w = (lane < rem) ? g_csr_w[e + lane]   : 0.f;
        for (int j = 0; j < rem; j++) {
            int   sj = __shfl_sync(0xffffffffu, s, j);
            float wj = __shfl_sync(0xffffffffu, w, j);
            float2 hv = hin2[(size_t)sj * 32 + lane];
            acc.x += hv.x * wj;
            acc.y += hv.y * wj;
        }
    }
    // self loop
    {
        float di = g_dinv[n];
        float wj = di * di;
        float2 hv = hin2[(size_t)n * 32 + lane];
        acc.x += hv.x * wj;
        acc.y += hv.y * wj;
    }
    // epilogue: fused bias+BN+ReLU
    const float* bnA = (POOL == 0) ? g_bnA1 : g_bnA2;
    const float* bnB = (POOL == 0) ? g_bnB1 : g_bnB2;
    float2 A = ((const float2*)bnA)[lane];
    float2 B = ((const float2*)bnB)[lane];
    float v0 = fmaxf(acc.x * A.x + B.x, 0.f);
    float v1 = fmaxf(acc.y * A.y + B.y, 0.f);
    if (POOL == 0) {
        ((float2*)g_h2)[(size_t)n * 32 + lane] = make_float2(v0, v1);
    } else {
        int g = load_idx(batch, n);
        atomicAdd(&g_pooled[g * HIDDEN + 2 * lane],     v0);
        atomicAdd(&g_pooled[g * HIDDEN + 2 * lane + 1], v1);
    }
}

// ---------------- final: out[g,c] = (pooled[g]/cnt) @ Wc + bc ----------------
__global__ void k_final(const float* __restrict__ Wc, const float* __restrict__ bc,
                        float* __restrict__ out) {
    int g = blockIdx.x * blockDim.x + threadIdx.x;
    if (g >= N_GRAPHS) return;
    float inv = 1.0f / fmaxf(g_gcount[g], 1.0f);
    float o0 = bc[0], o1 = bc[1], o2 = bc[2];
    #pragma unroll
    for (int h = 0; h < HIDDEN; h++) {
        float p = g_pooled[g * HIDDEN + h] * inv;
        o0 += p * Wc[h * N_CLASSES + 0];
        o1 += p * Wc[h * N_CLASSES + 1];
        o2 += p * Wc[h * N_CLASSES + 2];
    }
    out[g * N_CLASSES + 0] = o0;
    out[g * N_CLASSES + 1] = o1;
    out[g * N_CLASSES + 2] = o2;
}

// ---------------- launch ----------------
extern "C" void kernel_launch(void* const* d_in, const int* in_sizes, int n_in,
                              void* d_out, int out_size) {
    // size-based input mapping (robust to metadata ordering surprises)
    const float *x = 0, *W1 = 0, *W2 = 0, *Wc = 0, *bc = 0;
    const void  *ei = 0, *batch = 0;
    const float* v64[10] = {0};
    int n64 = 0;
    for (int i = 0; i < n_in; i++) {
        switch (in_sizes[i]) {
            case N_NODES * N_FEAT:   x     = (const float*)d_in[i]; break;  // 12.8M
            case 2 * N_EDGES:        ei    = d_in[i];               break;  // 6.4M
            case N_NODES:            batch = d_in[i];               break;  // 100K
            case N_FEAT * HIDDEN:    W1    = (const float*)d_in[i]; break;  // 8192
            case HIDDEN * HIDDEN:    W2    = (const float*)d_in[i]; break;  // 4096
            case HIDDEN * N_CLASSES: Wc    = (const float*)d_in[i]; break;  // 192
            case N_CLASSES:          bc    = (const float*)d_in[i]; break;  // 3
            case HIDDEN: if (n64 < 10) v64[n64++] = (const float*)d_in[i]; break;
        }
    }
    const float *b1 = v64[0], *gm1 = v64[1], *bt1 = v64[2], *rm1 = v64[3], *rv1 = v64[4];
    const float *b2 = v64[5], *gm2 = v64[6], *bt2 = v64[7], *rm2 = v64[8], *rv2 = v64[9];
    float* out = (float*)d_out;

    const int TB = 256;
    int nodeBlocks = (N_NODES + TB - 1) / TB;          // 391
    int edgeBlocks = (N_EDGES + TB - 1) / TB;          // 12500
    int gemmBlocks = (N_NODES + 63) / 64;              // 1563
    int convBlocks = (N_NODES * 32 + TB - 1) / TB;     // 12500 (warp per node)

    k_detect<<<1, 32>>>(ei);
    k_init<<<nodeBlocks, TB>>>();
    k_hist<<<edgeBlocks, TB>>>(ei);
    k_dinv<<<nodeBlocks, TB>>>(batch);
    k_scanA<<<SCAN_NB, SCAN_BS>>>();
    k_scanB<<<1, 32>>>();
    k_scanC<<<SCAN_NB, SCAN_BS>>>();
    k_fill<<<edgeBlocks, TB>>>(ei);
    k_bnprep<<<1, 64>>>(b1, gm1, bt1, rm1, rv1, b2, gm2, bt2, rm2, rv2);

    k_gemm64<N_FEAT, 0><<<gemmBlocks, 256>>>(x, W1, N_NODES);
    k_conv<0><<<convBlocks, TB>>>(batch);
    k_gemm64<HIDDEN, 1><<<gemmBlocks, 256>>>(nullptr, W2, N_NODES);
    k_conv<1><<<convBlocks, TB>>>(batch);
    k_final<<<2, 256>>>(Wc, bc, out);
}

// round 6
// speedup vs baseline: 1.1724x; 1.1724x over previous
#include <cuda_runtime.h>
#include <cuda_fp16.h>
#include <math.h>

// ---------------- problem constants ----------------
#define N_NODES   100000
#define N_EDGES   3200000
#define N_FEAT    128
#define HIDDEN    64
#define N_CLASSES 3
#define N_GRAPHS  512
#define BN_EPS    1e-5f

#define SCAN_BS   1024
#define SCAN_NB   ((N_NODES + SCAN_BS - 1) / SCAN_BS)   // 98

// ---------------- device scratch (no allocation allowed) ----------------
__device__ __align__(16) __half g_hs[(size_t)N_NODES * HIDDEN];  // dinv-scaled fp16 rows (conv gather input)
__device__ __align__(16) float  g_h2[(size_t)N_NODES * HIDDEN];  // conv1 output fp32 (gemm2 input)
__device__ int   g_csr_src[N_EDGES];
__device__ int   g_ptr[N_NODES + 1];
__device__ int   g_cnt[N_NODES];      // in-degree (no self loop)
__device__ int   g_cursor[N_NODES];
__device__ float g_dinv[N_NODES];
__device__ int   g_bsum[SCAN_NB + 1];
__device__ float g_pooled[N_GRAPHS * HIDDEN];
__device__ float g_gcount[N_GRAPHS];
__device__ __align__(16) float g_bnA1[HIDDEN], g_bnB1[HIDDEN], g_bnA2[HIDDEN], g_bnB2[HIDDEN];
__device__ int   g_idx64;             // 1 if edge/batch buffers are int64, 0 if int32

// flag-guarded index load (uniform branch; g_idx64 set before any use)
__device__ __forceinline__ int load_idx(const void* p, size_t i) {
    if (g_idx64) return (int)((const long long*)p)[i];
    return ((const int*)p)[i];
}

// ---------------- dtype detection ----------------
__global__ void k_detect(const void* ei) {
    if (threadIdx.x == 0) {
        const long long* p = (const long long*)ei;
        int ok = 1;
        for (int i = 0; i < 16; i++) {
            long long v = p[i];
            if (v < 0 || v >= N_NODES) ok = 0;
        }
        g_idx64 = ok;
    }
}

// ---------------- init ----------------
__global__ void k_init() {
    int i = blockIdx.x * blockDim.x + threadIdx.x;
    if (i < N_NODES) { g_cnt[i] = 0; g_cursor[i] = 0; }
    if (i < N_GRAPHS * HIDDEN) g_pooled[i] = 0.0f;
}

// histogram of dst
__global__ void k_hist(const void* __restrict__ ei) {
    int e = blockIdx.x * blockDim.x + threadIdx.x;
    if (e < N_EDGES) {
        int d = load_idx(ei, (size_t)N_EDGES + e);
        atomicAdd(&g_cnt[d], 1);
    }
}

// dinv = rsqrt(indeg+1)
__global__ void k_dinv() {
    int i = blockIdx.x * blockDim.x + threadIdx.x;
    if (i < N_NODES) g_dinv[i] = rsqrtf((float)(g_cnt[i] + 1));
}

// per-graph node counts via binary search (batch is sorted) — no atomics
__global__ void k_gcount(const void* __restrict__ batch) {
    int g = blockIdx.x * blockDim.x + threadIdx.x;
    if (g >= N_GRAPHS) return;
    int lo = 0, hi = N_NODES;
    while (lo < hi) { int m = (lo + hi) >> 1; if (load_idx(batch, m) < g) lo = m + 1; else hi = m; }
    int a = lo;
    lo = a; hi = N_NODES;
    while (lo < hi) { int m = (lo + hi) >> 1; if (load_idx(batch, m) < g + 1) lo = m + 1; else hi = m; }
    g_gcount[g] = (float)(lo - a);
}

// ---------------- 3-phase exclusive scan of g_cnt -> g_ptr ----------------
__global__ void k_scanA() {
    __shared__ int sm[SCAN_BS];
    int i = blockIdx.x * SCAN_BS + threadIdx.x;
    int v = (i < N_NODES) ? g_cnt[i] : 0;
    sm[threadIdx.x] = v;
    __syncthreads();
    for (int off = 1; off < SCAN_BS; off <<= 1) {
        int t = (threadIdx.x >= off) ? sm[threadIdx.x - off] : 0;
        __syncthreads();
        sm[threadIdx.x] += t;
        __syncthreads();
    }
    if (i < N_NODES) g_ptr[i] = sm[threadIdx.x] - v;  // exclusive
    if (threadIdx.x == SCAN_BS - 1) g_bsum[blockIdx.x] = sm[SCAN_BS - 1];
}

__global__ void k_scanB() {
    if (threadIdx.x == 0) {
        int acc = 0;
        for (int b = 0; b < SCAN_NB; b++) { int t = g_bsum[b]; g_bsum[b] = acc; acc += t; }
    }
}

__global__ void k_scanC() {
    int i = blockIdx.x * SCAN_BS + threadIdx.x;
    if (i < N_NODES) g_ptr[i] += g_bsum[blockIdx.x];
    if (i == 0) g_ptr[N_NODES] = N_EDGES;
}

// fill CSR: only src index (weights folded into scaled rows)
__global__ void k_fill(const void* __restrict__ ei) {
    int e = blockIdx.x * blockDim.x + threadIdx.x;
    if (e < N_EDGES) {
        int s = load_idx(ei, e);
        int d = load_idx(ei, (size_t)N_EDGES + e);
        int pos = atomicAdd(&g_cursor[d], 1);
        g_csr_src[g_ptr[d] + pos] = s;
    }
}

// fold bias + batchnorm into per-feature (A, B):  out = relu(acc*A + B)
__global__ void k_bnprep(const float* b1, const float* gm1, const float* bt1,
                         const float* rm1, const float* rv1,
                         const float* b2, const float* gm2, const float* bt2,
                         const float* rm2, const float* rv2) {
    int t = threadIdx.x;
    if (t < HIDDEN) {
        float a1 = gm1[t] * rsqrtf(rv1[t] + BN_EPS);
        g_bnA1[t] = a1;
        g_bnB1[t] = (b1[t] - rm1[t]) * a1 + bt1[t];
        float a2 = gm2[t] * rsqrtf(rv2[t] + BN_EPS);
        g_bnA2[t] = a2;
        g_bnB2[t] = (b2[t] - rm2[t]) * a2 + bt2[t];
    }
}

// ---------------- GEMM: g_hs[M,64](fp16) = (A[M,K] @ W[K,64]) * dinv[row] ----------------
// SRC==0: A = external x.  SRC==1: A = g_h2.
template<int K, int SRC>
__global__ void k_gemm64(const float* __restrict__ Aext, const float* __restrict__ W,
                         int M) {
    constexpr int KC = 64;
    __shared__ float sB[KC * 64];        // W chunk, row-major [k][64]
    __shared__ float sAT[KC * 68];       // A chunk transposed [k][row], pad 68
    const float* A = (SRC == 0) ? Aext : g_h2;
    int row0 = blockIdx.x * 64;
    int t  = threadIdx.x;
    int rq = t >> 4;      // 0..15 -> 4 rows each
    int cq = t & 15;      // 0..15 -> 4 cols each
    float acc[4][4];
    #pragma unroll
    for (int i = 0; i < 4; i++)
        #pragma unroll
        for (int j = 0; j < 4; j++) acc[i][j] = 0.0f;

    for (int k0 = 0; k0 < K; k0 += KC) {
        const float4* Wv = (const float4*)(W + (size_t)k0 * 64);
        float4* sBv = (float4*)sB;
        for (int i = t; i < KC * 16; i += 256) sBv[i] = Wv[i];
        for (int i = t; i < 64 * (KC / 4); i += 256) {
            int r  = i >> 4;            // 0..63
            int kk = (i & 15) << 2;     // 0,4,...,60
            float4 v = make_float4(0.f, 0.f, 0.f, 0.f);
            int row = row0 + r;
            if (row < M) v = *(const float4*)(A + (size_t)row * K + k0 + kk);
            sAT[(kk + 0) * 68 + r] = v.x;
            sAT[(kk + 1) * 68 + r] = v.y;
            sAT[(kk + 2) * 68 + r] = v.z;
            sAT[(kk + 3) * 68 + r] = v.w;
        }
        __syncthreads();
        #pragma unroll
        for (int k = 0; k < KC; k++) {
            float4 a = *(const float4*)&sAT[k * 68 + rq * 4];
            float4 b = *(const float4*)&sB[k * 64 + cq * 4];
            acc[0][0] += a.x * b.x; acc[0][1] += a.x * b.y; acc[0][2] += a.x * b.z; acc[0][3] += a.x * b.w;
            acc[1][0] += a.y * b.x; acc[1][1] += a.y * b.y; acc[1][2] += a.y * b.z; acc[1][3] += a.y * b.w;
            acc[2][0] += a.z * b.x; acc[2][1] += a.z * b.y; acc[2][2] += a.z * b.z; acc[2][3] += a.z * b.w;
            acc[3][0] += a.w * b.x; acc[3][1] += a.w * b.y; acc[3][2] += a.w * b.z; acc[3][3] += a.w * b.w;
        }
        __syncthreads();
    }
    #pragma unroll
    for (int ii = 0; ii < 4; ii++) {
        int row = row0 + rq * 4 + ii;
        if (row < M) {
            float d = g_dinv[row];
            __half2 lo = __floats2half2_rn(acc[ii][0] * d, acc[ii][1] * d);
            __half2 hi = __floats2half2_rn(acc[ii][2] * d, acc[ii][3] * d);
            __half2* dst = (__half2*)(g_hs + (size_t)row * 64 + cq * 4);
            dst[0] = lo;
            dst[1] = hi;
        }
    }
}

// ---------------- conv (pull, warp-per-node), reads g_hs (fp16, dinv-scaled) ----------------
// out_pre[n] = dinv[n] * (sum_{e in CSR} hs[src] + hs[n])
// POOL==0: g_h2[n] = relu(out_pre*A1 + B1)  (fp32)
// POOL==1: atomicAdd relu(out_pre*A2 + B2) into g_pooled[batch[n]]
template<int POOL>
__global__ void k_conv(const void* __restrict__ batch) {
    int warp = (blockIdx.x * blockDim.x + threadIdx.x) >> 5;
    int lane = threadIdx.x & 31;
    if (warp >= N_NODES) return;
    int n = warp;
    const __half2* hin = (const __half2*)g_hs;

    float2 acc = make_float2(0.f, 0.f);
    int start = g_ptr[n];
    int end   = g_ptr[n + 1];

    int e = start;
    for (; e + 32 <= end; e += 32) {
        int s = g_csr_src[e + lane];
        #pragma unroll
        for (int j = 0; j < 32; j++) {
            int sj = __shfl_sync(0xffffffffu, s, j);
            float2 hv = __half22float2(hin[(size_t)sj * 32 + lane]);
            acc.x += hv.x;
            acc.y += hv.y;
        }
    }
    int rem = end - e;
    if (rem > 0) {
        int s = (lane < rem) ? g_csr_src[e + lane] : 0;
        for (int j = 0; j < rem; j++) {
            int sj = __shfl_sync(0xffffffffu, s, j);
            float2 hv = __half22float2(hin[(size_t)sj * 32 + lane]);
            acc.x += hv.x;
            acc.y += hv.y;
        }
    }
    // self loop (hs[n] already carries dinv[n])
    {
        float2 hv = __half22float2(hin[(size_t)n * 32 + lane]);
        acc.x += hv.x;
        acc.y += hv.y;
    }
    float dn = g_dinv[n];
    const float* bnA = (POOL == 0) ? g_bnA1 : g_bnA2;
    const float* bnB = (POOL == 0) ? g_bnB1 : g_bnB2;
    float2 A = ((const float2*)bnA)[lane];
    float2 B = ((const float2*)bnB)[lane];
    float v0 = fmaxf(acc.x * dn * A.x + B.x, 0.f);
    float v1 = fmaxf(acc.y * dn * A.y + B.y, 0.f);
    if (POOL == 0) {
        ((float2*)g_h2)[(size_t)n * 32 + lane] = make_float2(v0, v1);
    } else {
        int g = load_idx(batch, n);
        atomicAdd(&g_pooled[g * HIDDEN + 2 * lane],     v0);
        atomicAdd(&g_pooled[g * HIDDEN + 2 * lane + 1], v1);
    }
}

// ---------------- final: out[g,c] = (pooled[g]/cnt) @ Wc + bc ----------------
__global__ void k_final(const float* __restrict__ Wc, const float* __restrict__ bc,
                        float* __restrict__ out) {
    int g = blockIdx.x * blockDim.x + threadIdx.x;
    if (g >= N_GRAPHS) return;
    float inv = 1.0f / fmaxf(g_gcount[g], 1.0f);
    float o0 = bc[0], o1 = bc[1], o2 = bc[2];
    #pragma unroll
    for (int h = 0; h < HIDDEN; h++) {
        float p = g_pooled[g * HIDDEN + h] * inv;
        o0 += p * Wc[h * N_CLASSES + 0];
        o1 += p * Wc[h * N_CLASSES + 1];
        o2 += p * Wc[h * N_CLASSES + 2];
    }
    out[g * N_CLASSES + 0] = o0;
    out[g * N_CLASSES + 1] = o1;
    out[g * N_CLASSES + 2] = o2;
}

// ---------------- launch ----------------
extern "C" void kernel_launch(void* const* d_in, const int* in_sizes, int n_in,
                              void* d_out, int out_size) {
    // size-based input mapping
    const float *x = 0, *W1 = 0, *W2 = 0, *Wc = 0, *bc = 0;
    const void  *ei = 0, *batch = 0;
    const float* v64[10] = {0};
    int n64 = 0;
    for (int i = 0; i < n_in; i++) {
        switch (in_sizes[i]) {
            case N_NODES * N_FEAT:   x     = (const float*)d_in[i]; break;  // 12.8M
            case 2 * N_EDGES:        ei    = d_in[i];               break;  // 6.4M
            case N_NODES:            batch = d_in[i];               break;  // 100K
            case N_FEAT * HIDDEN:    W1    = (const float*)d_in[i]; break;  // 8192
            case HIDDEN * HIDDEN:    W2    = (const float*)d_in[i]; break;  // 4096
            case HIDDEN * N_CLASSES: Wc    = (const float*)d_in[i]; break;  // 192
            case N_CLASSES:          bc    = (const float*)d_in[i]; break;  // 3
            case HIDDEN: if (n64 < 10) v64[n64++] = (const float*)d_in[i]; break;
        }
    }
    const float *b1 = v64[0], *gm1 = v64[1], *bt1 = v64[2], *rm1 = v64[3], *rv1 = v64[4];
    const float *b2 = v64[5], *gm2 = v64[6], *bt2 = v64[7], *rm2 = v64[8], *rv2 = v64[9];
    float* out = (float*)d_out;

    const int TB = 256;
    int nodeBlocks = (N_NODES + TB - 1) / TB;          // 391
    int edgeBlocks = (N_EDGES + TB - 1) / TB;          // 12500
    int gemmBlocks = (N_NODES + 63) / 64;              // 1563
    int convBlocks = (N_NODES * 32 + TB - 1) / TB;     // 12500 (warp per node)

    k_detect<<<1, 32>>>(ei);
    k_init<<<nodeBlocks, TB>>>();
    k_hist<<<edgeBlocks, TB>>>(ei);
    k_dinv<<<nodeBlocks, TB>>>();
    k_gcount<<<2, 256>>>(batch);
    k_scanA<<<SCAN_NB, SCAN_BS>>>();
    k_scanB<<<1, 32>>>();
    k_scanC<<<SCAN_NB, SCAN_BS>>>();
    k_fill<<<edgeBlocks, TB>>>(ei);
    k_bnprep<<<1, 64>>>(b1, gm1, bt1, rm1, rv1, b2, gm2, bt2, rm2, rv2);

    k_gemm64<N_FEAT, 0><<<gemmBlocks, 256>>>(x, W1, N_NODES);
    k_conv<0><<<convBlocks, TB>>>(batch);
    k_gemm64<HIDDEN, 1><<<gemmBlocks, 256>>>(nullptr, W2, N_NODES);
    k_conv<1><<<convBlocks, TB>>>(batch);
    k_final<<<2, 256>>>(Wc, bc, out);
}

// round 8
// speedup vs baseline: 1.3644x; 1.1637x over previous
#include <cuda_runtime.h>
#include <cuda_fp16.h>
#include <math.h>
#include <stdint.h>

// ---------------- problem constants ----------------
#define N_NODES   100000
#define N_EDGES   3200000
#define N_FEAT    128
#define HIDDEN    64
#define N_CLASSES 3
#define N_GRAPHS  512
#define BN_EPS    1e-5f

#define SCAN_BS   1024
#define SCAN_NB   ((N_NODES + SCAN_BS - 1) / SCAN_BS)   // 98

// ---------------- device scratch (no allocation allowed) ----------------
__device__ __align__(16) __half g_hs[(size_t)N_NODES * HIDDEN];  // dinv-scaled fp16 rows (conv gather input)
__device__ __align__(16) float  g_h2[(size_t)N_NODES * HIDDEN];  // conv1 output fp32 (gemm2 input)
__device__ int   g_csr_src[N_EDGES];
__device__ int   g_pos[N_EDGES];      // within-dst rank recorded by hist
__device__ int   g_ptr[N_NODES + 1];
__device__ int   g_cnt[N_NODES];      // in-degree (no self loop)
__device__ float g_dinv[N_NODES];
__device__ int   g_bsum[SCAN_NB + 1];
__device__ float g_pooled[N_GRAPHS * HIDDEN];
__device__ float g_gcount[N_GRAPHS];
__device__ __align__(16) float g_bnA1[HIDDEN], g_bnB1[HIDDEN], g_bnA2[HIDDEN], g_bnB2[HIDDEN];
__device__ int   g_idx64;             // 1 if edge/batch buffers are int64, 0 if int32

__device__ __forceinline__ int load_idx(const void* p, size_t i) {
    if (g_idx64) return (int)((const long long*)p)[i];
    return ((const int*)p)[i];
}

__device__ __forceinline__ uint32_t f2tf32(float x) {
    uint32_t y;
    asm("cvt.rna.tf32.f32 %0, %1;" : "=r"(y) : "f"(x));
    return y;
}

// ---------------- dtype detection ----------------
__global__ void k_detect(const void* ei) {
    if (threadIdx.x == 0) {
        const long long* p = (const long long*)ei;
        int ok = 1;
        for (int i = 0; i < 16; i++) {
            long long v = p[i];
            if (v < 0 || v >= N_NODES) ok = 0;
        }
        g_idx64 = ok;
    }
}

// ---------------- fused small prep: gcount (binary search) + bnprep + pooled init ----------------
__global__ void k_pre(const void* __restrict__ batch,
                      const float* b1, const float* gm1, const float* bt1,
                      const float* rm1, const float* rv1,
                      const float* b2, const float* gm2, const float* bt2,
                      const float* rm2, const float* rv2) {
    int gt = blockIdx.x * blockDim.x + threadIdx.x;   // 0..511
    if (gt < N_GRAPHS) {
        int g = gt;
        int lo = 0, hi = N_NODES;
        while (lo < hi) { int m = (lo + hi) >> 1; if (load_idx(batch, m) < g) lo = m + 1; else hi = m; }
        int a = lo;
        lo = a; hi = N_NODES;
        while (lo < hi) { int m = (lo + hi) >> 1; if (load_idx(batch, m) < g + 1) lo = m + 1; else hi = m; }
        g_gcount[g] = (float)(lo - a);
    }
    if (gt < HIDDEN) {
        float a1 = gm1[gt] * rsqrtf(rv1[gt] + BN_EPS);
        g_bnA1[gt] = a1;
        g_bnB1[gt] = (b1[gt] - rm1[gt]) * a1 + bt1[gt];
        float a2 = gm2[gt] * rsqrtf(rv2[gt] + BN_EPS);
        g_bnA2[gt] = a2;
        g_bnB2[gt] = (b2[gt] - rm2[gt]) * a2 + bt2[gt];
    }
    for (int i = gt; i < N_GRAPHS * HIDDEN; i += N_GRAPHS) g_pooled[i] = 0.0f;
}

// ---------------- init degree counters ----------------
__global__ void k_init() {
    int i = blockIdx.x * blockDim.x + threadIdx.x;
    if (i < N_NODES) g_cnt[i] = 0;
}

// histogram of dst; record within-dst position (atomic return value)
__global__ void k_hist(const void* __restrict__ ei) {
    int e = blockIdx.x * blockDim.x + threadIdx.x;
    if (e < N_EDGES) {
        int d = load_idx(ei, (size_t)N_EDGES + e);
        g_pos[e] = atomicAdd(&g_cnt[d], 1);
    }
}

// ---------------- 3-phase exclusive scan of g_cnt -> g_ptr (+ dinv fused) ----------------
__global__ void k_scanA() {
    __shared__ int sm[SCAN_BS];
    int i = blockIdx.x * SCAN_BS + threadIdx.x;
    int v = (i < N_NODES) ? g_cnt[i] : 0;
    if (i < N_NODES) g_dinv[i] = rsqrtf((float)(v + 1));
    sm[threadIdx.x] = v;
    __syncthreads();
    for (int off = 1; off < SCAN_BS; off <<= 1) {
        int t = (threadIdx.x >= off) ? sm[threadIdx.x - off] : 0;
        __syncthreads();
        sm[threadIdx.x] += t;
        __syncthreads();
    }
    if (i < N_NODES) g_ptr[i] = sm[threadIdx.x] - v;  // exclusive
    if (threadIdx.x == SCAN_BS - 1) g_bsum[blockIdx.x] = sm[SCAN_BS - 1];
}

__global__ void k_scanB() {
    if (threadIdx.x == 0) {
        int acc = 0;
        for (int b = 0; b < SCAN_NB; b++) { int t = g_bsum[b]; g_bsum[b] = acc; acc += t; }
    }
}

__global__ void k_scanC() {
    int i = blockIdx.x * SCAN_BS + threadIdx.x;
    if (i < N_NODES) g_ptr[i] += g_bsum[blockIdx.x];
    if (i == 0) g_ptr[N_NODES] = N_EDGES;
}

// fill CSR: atomic-free (uses recorded position)
__global__ void k_fill(const void* __restrict__ ei) {
    int e = blockIdx.x * blockDim.x + threadIdx.x;
    if (e < N_EDGES) {
        int s = load_idx(ei, e);
        int d = load_idx(ei, (size_t)N_EDGES + e);
        g_csr_src[g_ptr[d] + g_pos[e]] = s;
    }
}

// ---------------- tensor-core GEMM (tf32 mma.sync m16n8k8) ----------------
// g_hs[M,64](fp16) = (A[M,K] @ W[K,64]) * dinv[row]
// SRC==0: A = external x.  SRC==1: A = g_h2.
// Block: 128 threads (4 warps); tile 64 rows x 64 cols; k-outer in 64 chunks.
template<int K, int SRC>
__global__ void k_gemm_tc(const float* __restrict__ Aext, const float* __restrict__ W,
                          int M) {
    __shared__ uint32_t sA[64 * 68];   // A chunk [row][k], stride 68 (conflict-free frag loads)
    __shared__ uint32_t sW[64 * 72];   // W chunk [k][n],  stride 72 (conflict-free frag loads)
    const float* A = (SRC == 0) ? Aext : g_h2;
    int row0 = blockIdx.x * 64;
    int t    = threadIdx.x;
    int w    = t >> 5;
    int lane = t & 31;
    int g    = lane >> 2;    // groupID 0..7
    int tig  = lane & 3;     // thread-in-group 0..3

    float acc[8][4];
    #pragma unroll
    for (int nt = 0; nt < 8; nt++)
        #pragma unroll
        for (int j = 0; j < 4; j++) acc[nt][j] = 0.0f;

    for (int k0 = 0; k0 < K; k0 += 64) {
        // stage W chunk [64 k][64 n] -> sW (tf32)
        for (int i = t; i < 64 * 16; i += 128) {
            int r = i >> 4;
            int c = (i & 15) << 2;
            float4 v = *(const float4*)(W + (size_t)(k0 + r) * 64 + c);
            sW[r * 72 + c + 0] = f2tf32(v.x);
            sW[r * 72 + c + 1] = f2tf32(v.y);
            sW[r * 72 + c + 2] = f2tf32(v.z);
            sW[r * 72 + c + 3] = f2tf32(v.w);
        }
        // stage A chunk [64 row][64 k] -> sA (tf32), zero-pad OOB rows
        for (int i = t; i < 64 * 16; i += 128) {
            int r = i >> 4;
            int c = (i & 15) << 2;
            int row = row0 + r;
            float4 v = make_float4(0.f, 0.f, 0.f, 0.f);
            if (row < M) v = *(const float4*)(A + (size_t)row * K + k0 + c);
            sA[r * 68 + c + 0] = f2tf32(v.x);
            sA[r * 68 + c + 1] = f2tf32(v.y);
            sA[r * 68 + c + 2] = f2tf32(v.z);
            sA[r * 68 + c + 3] = f2tf32(v.w);
        }
        __syncthreads();
        #pragma unroll
        for (int kc = 0; kc < 8; kc++) {
            int kk = kc * 8;
            uint32_t a0 = sA[(w * 16 + g)     * 68 + kk + tig];
            uint32_t a1 = sA[(w * 16 + g + 8) * 68 + kk + tig];
            uint32_t a2 = sA[(w * 16 + g)     * 68 + kk + tig + 4];
            uint32_t a3 = sA[(w * 16 + g + 8) * 68 + kk + tig + 4];
            #pragma unroll
            for (int nt = 0; nt < 8; nt++) {
                uint32_t b0 = sW[(kk + tig)     * 72 + nt * 8 + g];
                uint32_t b1 = sW[(kk + tig + 4) * 72 + nt * 8 + g];
                asm volatile(
                    "mma.sync.aligned.m16n8k8.row.col.f32.tf32.tf32.f32 "
                    "{%0,%1,%2,%3}, {%4,%5,%6,%7}, {%8,%9}, {%0,%1,%2,%3};"
                    : "+f"(acc[nt][0]), "+f"(acc[nt][1]), "+f"(acc[nt][2]), "+f"(acc[nt][3])
                    : "r"(a0), "r"(a1), "r"(a2), "r"(a3), "r"(b0), "r"(b1));
            }
        }
        __syncthreads();
    }
    // epilogue: scale by dinv, convert to fp16, store
    int r0 = row0 + w * 16 + g;
    int r1 = r0 + 8;
    if (r0 < M) {
        float d = g_dinv[r0];
        #pragma unroll
        for (int nt = 0; nt < 8; nt++) {
            __half2 v = __floats2half2_rn(acc[nt][0] * d, acc[nt][1] * d);
            *(__half2*)(g_hs + (size_t)r0 * 64 + nt * 8 + 2 * tig) = v;
        }
    }
    if (r1 < M) {
        float d = g_dinv[r1];
        #pragma unroll
        for (int nt = 0; nt < 8; nt++) {
            __half2 v = __floats2half2_rn(acc[nt][2] * d, acc[nt][3] * d);
            *(__half2*)(g_hs + (size_t)r1 * 64 + nt * 8 + 2 * tig) = v;
        }
    }
}

// ---------------- conv (pull, warp-per-node), reads g_hs (fp16, dinv-scaled) ----------------
// out_pre[n] = dinv[n] * (sum_{e in CSR} hs[src] + hs[n])
// POOL==0: g_h2[n] = relu(out_pre*A1 + B1)  (fp32)
// POOL==1: atomicAdd relu(out_pre*A2 + B2) into g_pooled[batch[n]]
template<int POOL>
__global__ void k_conv(const void* __restrict__ batch) {
    int warp = (blockIdx.x * blockDim.x + threadIdx.x) >> 5;
    int lane = threadIdx.x & 31;
    if (warp >= N_NODES) return;
    int n = warp;
    const __half2* hin = (const __half2*)g_hs;

    float2 acc = make_float2(0.f, 0.f);
    int start = g_ptr[n];
    int end   = g_ptr[n + 1];

    int e = start;
    for (; e + 32 <= end; e += 32) {
        int s = g_csr_src[e + lane];
        #pragma unroll
        for (int j = 0; j < 32; j++) {
            int sj = __shfl_sync(0xffffffffu, s, j);
            float2 hv = __half22float2(hin[(size_t)sj * 32 + lane]);
            acc.x += hv.x;
            acc.y += hv.y;
        }
    }
    int rem = end - e;
    if (rem > 0) {
        int s = (lane < rem) ? g_csr_src[e + lane] : 0;
        for (int j = 0; j < rem; j++) {
            int sj = __shfl_sync(0xffffffffu, s, j);
            float2 hv = __half22float2(hin[(size_t)sj * 32 + lane]);
            acc.x += hv.x;
            acc.y += hv.y;
        }
    }
    // self loop (hs[n] already carries dinv[n])
    {
        float2 hv = __half22float2(hin[(size_t)n * 32 + lane]);
        acc.x += hv.x;
        acc.y += hv.y;
    }
    float dn = g_dinv[n];
    const float* bnA = (POOL == 0) ? g_bnA1 : g_bnA2;
    const float* bnB = (POOL == 0) ? g_bnB1 : g_bnB2;
    float2 A = ((const float2*)bnA)[lane];
    float2 B = ((const float2*)bnB)[lane];
    float v0 = fmaxf(acc.x * dn * A.x + B.x, 0.f);
    float v1 = fmaxf(acc.y * dn * A.y + B.y, 0.f);
    if (POOL == 0) {
        ((float2*)g_h2)[(size_t)n * 32 + lane] = make_float2(v0, v1);
    } else {
        int g = load_idx(batch, n);
        atomicAdd(&g_pooled[g * HIDDEN + 2 * lane],     v0);
        atomicAdd(&g_pooled[g * HIDDEN + 2 * lane + 1], v1);
    }
}

// ---------------- final: out[g,c] = (pooled[g]/cnt) @ Wc + bc ----------------
__global__ void k_final(const float* __restrict__ Wc, const float* __restrict__ bc,
                        float* __restrict__ out) {
    int g = blockIdx.x * blockDim.x + threadIdx.x;
    if (g >= N_GRAPHS) return;
    float inv = 1.0f / fmaxf(g_gcount[g], 1.0f);
    float o0 = bc[0], o1 = bc[1], o2 = bc[2];
    #pragma unroll
    for (int h = 0; h < HIDDEN; h++) {
        float p = g_pooled[g * HIDDEN + h] * inv;
        o0 += p * Wc[h * N_CLASSES + 0];
        o1 += p * Wc[h * N_CLASSES + 1];
        o2 += p * Wc[h * N_CLASSES + 2];
    }
    out[g * N_CLASSES + 0] = o0;
    out[g * N_CLASSES + 1] = o1;
    out[g * N_CLASSES + 2] = o2;
}

// ---------------- launch ----------------
extern "C" void kernel_launch(void* const* d_in, const int* in_sizes, int n_in,
                              void* d_out, int out_size) {
    // size-based input mapping
    const float *x = 0, *W1 = 0, *W2 = 0, *Wc = 0, *bc = 0;
    const void  *ei = 0, *batch = 0;
    const float* v64[10] = {0};
    int n64 = 0;
    for (int i = 0; i < n_in; i++) {
        switch (in_sizes[i]) {
            case N_NODES * N_FEAT:   x     = (const float*)d_in[i]; break;  // 12.8M
            case 2 * N_EDGES:        ei    = d_in[i];               break;  // 6.4M
            case N_NODES:            batch = d_in[i];               break;  // 100K
            case N_FEAT * HIDDEN:    W1    = (const float*)d_in[i]; break;  // 8192
            case HIDDEN * HIDDEN:    W2    = (const float*)d_in[i]; break;  // 4096
            case HIDDEN * N_CLASSES: Wc    = (const float*)d_in[i]; break;  // 192
            case N_CLASSES:          bc    = (const float*)d_in[i]; break;  // 3
            case HIDDEN: if (n64 < 10) v64[n64++] = (const float*)d_in[i]; break;
        }
    }
    const float *b1 = v64[0], *gm1 = v64[1], *bt1 = v64[2], *rm1 = v64[3], *rv1 = v64[4];
    const float *b2 = v64[5], *gm2 = v64[6], *bt2 = v64[7], *rm2 = v64[8], *rv2 = v64[9];
    float* out = (float*)d_out;

    const int TB = 256;
    int nodeBlocks = (N_NODES + TB - 1) / TB;          // 391
    int edgeBlocks = (N_EDGES + TB - 1) / TB;          // 12500
    int gemmBlocks = (N_NODES + 63) / 64;              // 1563
    int convBlocks = (N_NODES * 32 + TB - 1) / TB;     // 12500 (warp per node)

    k_detect<<<1, 32>>>(ei);
    k_pre<<<2, 256>>>(batch, b1, gm1, bt1, rm1, rv1, b2, gm2, bt2, rm2, rv2);
    k_init<<<nodeBlocks, TB>>>();
    k_hist<<<edgeBlocks, TB>>>(ei);
    k_scanA<<<SCAN_NB, SCAN_BS>>>();
    k_scanB<<<1, 32>>>();
    k_scanC<<<SCAN_NB, SCAN_BS>>>();
    k_fill<<<edgeBlocks, TB>>>(ei);

    k_gemm_tc<N_FEAT, 0><<<gemmBlocks, 128>>>(x, W1, N_NODES);
    k_conv<0><<<convBlocks, TB>>>(batch);
    k_gemm_tc<HIDDEN, 1><<<gemmBlocks, 128>>>(nullptr, W2, N_NODES);
    k_conv<1><<<convBlocks, TB>>>(batch);
    k_final<<<2, 256>>>(Wc, bc, out);
}

// round 10
// speedup vs baseline: 1.3791x; 1.0108x over previous
#include <cuda_runtime.h>
#include <cuda_fp16.h>
#include <math.h>
#include <stdint.h>

// ---------------- problem constants ----------------
#define N_NODES   100000
#define N_EDGES   3200000
#define N_FEAT    128
#define HIDDEN    64
#define N_CLASSES 3
#define N_GRAPHS  512
#define BN_EPS    1e-5f

#define SCAN_BS   1024
#define SCAN_NB   ((N_NODES + SCAN_BS - 1) / SCAN_BS)   // 98

// ---------------- device scratch (no allocation allowed) ----------------
__device__ __align__(16) __half g_hs[(size_t)N_NODES * HIDDEN];  // dinv-scaled fp16 rows (conv gather input)
__device__ __align__(16) float  g_h2[(size_t)N_NODES * HIDDEN];  // conv1 output fp32 (gemm2 input)
__device__ int      g_csr_src[N_EDGES];
__device__ uint32_t g_dp[N_EDGES];    // packed (dst<<15 | pos) recorded by hist
__device__ int      g_ptr[N_NODES];   // block-local exclusive scan (finalized via g_bsum)
__device__ int      g_cnt[N_NODES];   // in-degree (no self loop)
__device__ float    g_dinv[N_NODES];
__device__ int      g_bsum[SCAN_NB + 1];
__device__ float    g_pooled[N_GRAPHS * HIDDEN];
__device__ float    g_gcount[N_GRAPHS];
__device__ __align__(16) float g_bnA1[HIDDEN], g_bnB1[HIDDEN], g_bnA2[HIDDEN], g_bnB2[HIDDEN];
__device__ int      g_idx64;          // 1 if edge/batch buffers are int64, 0 if int32

__device__ __forceinline__ int load_idx(const void* p, size_t i) {
    if (g_idx64) return (int)((const long long*)p)[i];
    return ((const int*)p)[i];
}

__device__ __forceinline__ uint32_t f2tf32(float x) {
    uint32_t y;
    asm("cvt.rna.tf32.f32 %0, %1;" : "=r"(y) : "f"(x));
    return y;
}

// final CSR offset for node n (g_ptr holds block-local scan; g_bsum holds block prefix)
__device__ __forceinline__ int ptr_of(int n) {
    if (n >= N_NODES) return N_EDGES;
    return g_ptr[n] + g_bsum[n >> 10];
}

// ---------------- init: zero degree counters + pooled ----------------
__global__ void k_init() {
    int i = blockIdx.x * blockDim.x + threadIdx.x;
    if (i < N_NODES) g_cnt[i] = 0;
    if (i < N_GRAPHS * HIDDEN) g_pooled[i] = 0.0f;
}

// ---------------- fused prep (single block, 512 thr): detect + gcount + bnprep ----------------
__global__ void k_pre(const void* __restrict__ ei, const void* __restrict__ batch,
                      const float* b1, const float* gm1, const float* bt1,
                      const float* rm1, const float* rv1,
                      const float* b2, const float* gm2, const float* bt2,
                      const float* rm2, const float* rv2) {
    int t = threadIdx.x;
    // phase 1: parallel dtype detect (16 lanes probe int64 interpretation)
    if (t < 32) {
        const long long* p = (const long long*)ei;
        int bad = 0;
        if (t < 16) {
            long long v = p[t];
            bad = (v < 0 || v >= N_NODES);
        }
        unsigned m = __ballot_sync(0xffffffffu, bad);
        if (t == 0) g_idx64 = (m == 0u);
    }
    __syncthreads();   // g_idx64 visible block-wide
    // phase 2: per-graph node counts via binary search (batch sorted)
    if (t < N_GRAPHS) {
        int g = t;
        int lo = 0, hi = N_NODES;
        while (lo < hi) { int m = (lo + hi) >> 1; if (load_idx(batch, m) < g) lo = m + 1; else hi = m; }
        int a = lo;
        lo = a; hi = N_NODES;
        while (lo < hi) { int m = (lo + hi) >> 1; if (load_idx(batch, m) < g + 1) lo = m + 1; else hi = m; }
        g_gcount[g] = (float)(lo - a);
    }
    // phase 3: fold bias+BN into per-feature affine
    if (t < HIDDEN) {
        float a1 = gm1[t] * rsqrtf(rv1[t] + BN_EPS);
        g_bnA1[t] = a1;
        g_bnB1[t] = (b1[t] - rm1[t]) * a1 + bt1[t];
        float a2 = gm2[t] * rsqrtf(rv2[t] + BN_EPS);
        g_bnA2[t] = a2;
        g_bnB2[t] = (b2[t] - rm2[t]) * a2 + bt2[t];
    }
}

// ---------------- histogram of dst; record packed (dst,pos) ----------------
__global__ void k_hist(const void* __restrict__ ei) {
    int e = blockIdx.x * blockDim.x + threadIdx.x;
    if (e < N_EDGES) {
        int d = load_idx(ei, (size_t)N_EDGES + e);
        uint32_t pos = (uint32_t)atomicAdd(&g_cnt[d], 1);
        g_dp[e] = ((uint32_t)d << 15) | pos;
    }
}

// ---------------- scan: block-local exclusive (+dinv fused), then parallel block-sum scan ----------------
__global__ void k_scanA() {
    __shared__ int sm[SCAN_BS];
    int i = blockIdx.x * SCAN_BS + threadIdx.x;
    int v = (i < N_NODES) ? g_cnt[i] : 0;
    if (i < N_NODES) g_dinv[i] = rsqrtf((float)(v + 1));
    sm[threadIdx.x] = v;
    __syncthreads();
    for (int off = 1; off < SCAN_BS; off <<= 1) {
        int t = (threadIdx.x >= off) ? sm[threadIdx.x - off] : 0;
        __syncthreads();
        sm[threadIdx.x] += t;
        __syncthreads();
    }
    if (i < N_NODES) g_ptr[i] = sm[threadIdx.x] - v;  // exclusive within block
    if (threadIdx.x == SCAN_BS - 1) g_bsum[blockIdx.x] = sm[SCAN_BS - 1];
}

__global__ void k_scanB() {   // 1 block, 128 threads: exclusive scan of 98 block sums
    __shared__ int sm[128];
    int t = threadIdx.x;
    int v = (t < SCAN_NB) ? g_bsum[t] : 0;
    sm[t] = v;
    __syncthreads();
    for (int off = 1; off < 128; off <<= 1) {
        int u = (t >= off) ? sm[t - off] : 0;
        __syncthreads();
        sm[t] += u;
        __syncthreads();
    }
    if (t < SCAN_NB) g_bsum[t] = sm[t] - v;   // exclusive
}

// ---------------- fill CSR: atomic-free, reads only src + packed ----------------
__global__ void k_fill(const void* __restrict__ ei) {
    int e = blockIdx.x * blockDim.x + threadIdx.x;
    if (e < N_EDGES) {
        int s = load_idx(ei, e);
        uint32_t dp = g_dp[e];
        int d   = (int)(dp >> 15);
        int pos = (int)(dp & 0x7fffu);
        g_csr_src[g_ptr[d] + g_bsum[d >> 10] + pos] = s;
    }
}

// ---------------- tensor-core GEMM (tf32 mma.sync m16n8k8) ----------------
// g_hs[M,64](fp16) = (A[M,K] @ W[K,64]) * dinv[row]
template<int K, int SRC>
__global__ void k_gemm_tc(const float* __restrict__ Aext, const float* __restrict__ W,
                          int M) {
    __shared__ uint32_t sA[64 * 68];
    __shared__ uint32_t sW[64 * 72];
    const float* A = (SRC == 0) ? Aext : g_h2;
    int row0 = blockIdx.x * 64;
    int t    = threadIdx.x;
    int w    = t >> 5;
    int lane = t & 31;
    int g    = lane >> 2;
    int tig  = lane & 3;

    float acc[8][4];
    #pragma unroll
    for (int nt = 0; nt < 8; nt++)
        #pragma unroll
        for (int j = 0; j < 4; j++) acc[nt][j] = 0.0f;

    for (int k0 = 0; k0 < K; k0 += 64) {
        for (int i = t; i < 64 * 16; i += 128) {
            int r = i >> 4;
            int c = (i & 15) << 2;
            float4 v = *(const float4*)(W + (size_t)(k0 + r) * 64 + c);
            sW[r * 72 + c + 0] = f2tf32(v.x);
            sW[r * 72 + c + 1] = f2tf32(v.y);
            sW[r * 72 + c + 2] = f2tf32(v.z);
            sW[r * 72 + c + 3] = f2tf32(v.w);
        }
        for (int i = t; i < 64 * 16; i += 128) {
            int r = i >> 4;
            int c = (i & 15) << 2;
            int row = row0 + r;
            float4 v = make_float4(0.f, 0.f, 0.f, 0.f);
            if (row < M) v = *(const float4*)(A + (size_t)row * K + k0 + c);
            sA[r * 68 + c + 0] = f2tf32(v.x);
            sA[r * 68 + c + 1] = f2tf32(v.y);
            sA[r * 68 + c + 2] = f2tf32(v.z);
            sA[r * 68 + c + 3] = f2tf32(v.w);
        }
        __syncthreads();
        #pragma unroll
        for (int kc = 0; kc < 8; kc++) {
            int kk = kc * 8;
            uint32_t a0 = sA[(w * 16 + g)     * 68 + kk + tig];
            uint32_t a1 = sA[(w * 16 + g + 8) * 68 + kk + tig];
            uint32_t a2 = sA[(w * 16 + g)     * 68 + kk + tig + 4];
            uint32_t a3 = sA[(w * 16 + g + 8) * 68 + kk + tig + 4];
            #pragma unroll
            for (int nt = 0; nt < 8; nt++) {
                uint32_t b0 = sW[(kk + tig)     * 72 + nt * 8 + g];
                uint32_t b1 = sW[(kk + tig + 4) * 72 + nt * 8 + g];
                asm volatile(
                    "mma.sync.aligned.m16n8k8.row.col.f32.tf32.tf32.f32 "
                    "{%0,%1,%2,%3}, {%4,%5,%6,%7}, {%8,%9}, {%0,%1,%2,%3};"
                    : "+f"(acc[nt][0]), "+f"(acc[nt][1]), "+f"(acc[nt][2]), "+f"(acc[nt][3])
                    : "r"(a0), "r"(a1), "r"(a2), "r"(a3), "r"(b0), "r"(b1));
            }
        }
        __syncthreads();
    }
    int r0 = row0 + w * 16 + g;
    int r1 = r0 + 8;
    if (r0 < M) {
        float d = g_dinv[r0];
        #pragma unroll
        for (int nt = 0; nt < 8; nt++) {
            __half2 v = __floats2half2_rn(acc[nt][0] * d, acc[nt][1] * d);
            *(__half2*)(g_hs + (size_t)r0 * 64 + nt * 8 + 2 * tig) = v;
        }
    }
    if (r1 < M) {
        float d = g_dinv[r1];
        #pragma unroll
        for (int nt = 0; nt < 8; nt++) {
            __half2 v = __floats2half2_rn(acc[nt][2] * d, acc[nt][3] * d);
            *(__half2*)(g_hs + (size_t)r1 * 64 + nt * 8 + 2 * tig) = v;
        }
    }
}

// ---------------- conv (pull, warp-per-node), reads g_hs (fp16, dinv-scaled) ----------------
template<int POOL>
__global__ void k_conv(const void* __restrict__ batch) {
    int warp = (blockIdx.x * blockDim.x + threadIdx.x) >> 5;
    int lane = threadIdx.x & 31;
    if (warp >= N_NODES) return;
    int n = warp;
    const __half2* hin = (const __half2*)g_hs;

    float2 acc = make_float2(0.f, 0.f);
    int start = ptr_of(n);
    int end   = ptr_of(n + 1);

    int e = start;
    for (; e + 32 <= end; e += 32) {
        int s = g_csr_src[e + lane];
        #pragma unroll
        for (int j = 0; j < 32; j++) {
            int sj = __shfl_sync(0xffffffffu, s, j);
            float2 hv = __half22float2(hin[(size_t)sj * 32 + lane]);
            acc.x += hv.x;
            acc.y += hv.y;
        }
    }
    int rem = end - e;
    if (rem > 0) {
        int s = (lane < rem) ? g_csr_src[e + lane] : 0;
        for (int j = 0; j < rem; j++) {
            int sj = __shfl_sync(0xffffffffu, s, j);
            float2 hv = __half22float2(hin[(size_t)sj * 32 + lane]);
            acc.x += hv.x;
            acc.y += hv.y;
        }
    }
    // self loop (hs[n] already carries dinv[n])
    {
        float2 hv = __half22float2(hin[(size_t)n * 32 + lane]);
        acc.x += hv.x;
        acc.y += hv.y;
    }
    float dn = g_dinv[n];
    const float* bnA = (POOL == 0) ? g_bnA1 : g_bnA2;
    const float* bnB = (POOL == 0) ? g_bnB1 : g_bnB2;
    float2 A = ((const float2*)bnA)[lane];
    float2 B = ((const float2*)bnB)[lane];
    float v0 = fmaxf(acc.x * dn * A.x + B.x, 0.f);
    float v1 = fmaxf(acc.y * dn * A.y + B.y, 0.f);
    if (POOL == 0) {
        ((float2*)g_h2)[(size_t)n * 32 + lane] = make_float2(v0, v1);
    } else {
        int g = load_idx(batch, n);
        atomicAdd(&g_pooled[g * HIDDEN + 2 * lane],     v0);
        atomicAdd(&g_pooled[g * HIDDEN + 2 * lane + 1], v1);
    }
}

// ---------------- final: out[g,c] = (pooled[g]/cnt) @ Wc + bc ----------------
__global__ void k_final(const float* __restrict__ Wc, const float* __restrict__ bc,
                        float* __restrict__ out) {
    int g = blockIdx.x * blockDim.x + threadIdx.x;
    if (g >= N_GRAPHS) return;
    float inv = 1.0f / fmaxf(g_gcount[g], 1.0f);
    float o0 = bc[0], o1 = bc[1], o2 = bc[2];
    #pragma unroll
    for (int h = 0; h < HIDDEN; h++) {
        float p = g_pooled[g * HIDDEN + h] * inv;
        o0 += p * Wc[h * N_CLASSES + 0];
        o1 += p * Wc[h * N_CLASSES + 1];
        o2 += p * Wc[h * N_CLASSES + 2];
    }
    out[g * N_CLASSES + 0] = o0;
    out[g * N_CLASSES + 1] = o1;
    out[g * N_CLASSES + 2] = o2;
}

// ---------------- launch ----------------
extern "C" void kernel_launch(void* const* d_in, const int* in_sizes, int n_in,
                              void* d_out, int out_size) {
    const float *x = 0, *W1 = 0, *W2 = 0, *Wc = 0, *bc = 0;
    const void  *ei = 0, *batch = 0;
    const float* v64[10] = {0};
    int n64 = 0;
    for (int i = 0; i < n_in; i++) {
        switch (in_sizes[i]) {
            case N_NODES * N_FEAT:   x     = (const float*)d_in[i]; break;
            case 2 * N_EDGES:        ei    = d_in[i];               break;
            case N_NODES:            batch = d_in[i];               break;
            case N_FEAT * HIDDEN:    W1    = (const float*)d_in[i]; break;
            case HIDDEN * HIDDEN:    W2    = (const float*)d_in[i]; break;
            case HIDDEN * N_CLASSES: Wc    = (const float*)d_in[i]; break;
            case N_CLASSES:          bc    = (const float*)d_in[i]; break;
            case HIDDEN: if (n64 < 10) v64[n64++] = (const float*)d_in[i]; break;
        }
    }
    const float *b1 = v64[0], *gm1 = v64[1], *bt1 = v64[2], *rm1 = v64[3], *rv1 = v64[4];
    const float *b2 = v64[5], *gm2 = v64[6], *bt2 = v64[7], *rm2 = v64[8], *rv2 = v64[9];
    float* out = (float*)d_out;

    const int TB = 256;
    int nodeBlocks = (N_NODES + TB - 1) / TB;          // 391
    int edgeBlocks = (N_EDGES + TB - 1) / TB;          // 12500
    int gemmBlocks = (N_NODES + 63) / 64;              // 1563
    int convBlocks = (N_NODES * 32 + TB - 1) / TB;     // 12500 (warp per node)

    k_pre<<<1, 512>>>(ei, batch, b1, gm1, bt1, rm1, rv1, b2, gm2, bt2, rm2, rv2);
    k_init<<<nodeBlocks, TB>>>();
    k_hist<<<edgeBlocks, TB>>>(ei);
    k_scanA<<<SCAN_NB, SCAN_BS>>>();
    k_scanB<<<1, 128>>>();
    k_fill<<<edgeBlocks, TB>>>(ei);

    k_gemm_tc<N_FEAT, 0><<<gemmBlocks, 128>>>(x, W1, N_NODES);
    k_conv<0><<<convBlocks, TB>>>(batch);
    k_gemm_tc<HIDDEN, 1><<<gemmBlocks, 128>>>(nullptr, W2, N_NODES);
    k_conv<1><<<convBlocks, TB>>>(batch);
    k_final<<<2, 256>>>(Wc, bc, out);
}